// round 9
// baseline (speedup 1.0000x reference)
#include <cuda_runtime.h>
#include <cuda_bf16.h>
#include <cstdint>

#define NN 4096
#define FF 512
#define DD 128
#define HH 8
#define KC 64
#define NCHUNK (NN / KC)

// ---------------- scratch (static device globals; no allocs) ----------------
__device__ __nv_bfloat16 g_featb[NN * FF];          // 4 MB
__device__ __nv_bfloat16 g_Wb[HH * FF * DD];        // 1 MB
__device__ __nv_bfloat16 g_Bp[HH * NN * 136];       // 8.9 MB: [h][j][0:128]=e2p*Wh, [128]=e2p, [129:136]=0
__device__ float g_ratio[HH * NN];                  // r_i = exp(-0.8 s1)
__device__ __nv_bfloat16 g_e2rb[HH * NN];           // e2r_j = exp(-0.8 s2), bf16
__device__ unsigned g_adjbits[NN * (NN / 32)];      // 2 MB
__device__ float g_haccum[HH * NN * DD];            // 16 MB per-head elu(h')

// ---------------- helpers ----------------
__device__ __forceinline__ unsigned pack_bf16x2(float lo, float hi) {
    unsigned r;
    asm("cvt.rn.bf16x2.f32 %0, %1, %2;" : "=r"(r) : "f"(hi), "f"(lo));
    return r;
}
__device__ __forceinline__ unsigned smem_u32(const void* p) {
    return (unsigned)__cvta_generic_to_shared(p);
}
__device__ __forceinline__ unsigned SWZ(unsigned off) {        // SW128 swizzle
    return off ^ ((off >> 3) & 0x70);
}
__device__ __forceinline__ void ldsm_x4(unsigned addr, unsigned& r0, unsigned& r1,
                                        unsigned& r2, unsigned& r3) {
    asm volatile("ldmatrix.sync.aligned.m8n8.x4.shared.b16 {%0,%1,%2,%3}, [%4];"
                 : "=r"(r0), "=r"(r1), "=r"(r2), "=r"(r3) : "r"(addr));
}
__device__ __forceinline__ void ldsm_x4_t(unsigned addr, unsigned& r0, unsigned& r1,
                                          unsigned& r2, unsigned& r3) {
    asm volatile("ldmatrix.sync.aligned.m8n8.x4.trans.shared.b16 {%0,%1,%2,%3}, [%4];"
                 : "=r"(r0), "=r"(r1), "=r"(r2), "=r"(r3) : "r"(addr));
}
__device__ __forceinline__ void ldsm_x2_t(unsigned addr, unsigned& r0, unsigned& r1) {
    asm volatile("ldmatrix.sync.aligned.m8n8.x2.trans.shared.b16 {%0,%1}, [%2];"
                 : "=r"(r0), "=r"(r1) : "r"(addr));
}
__device__ __forceinline__ void mma_bf16(float* c, unsigned a0, unsigned a1, unsigned a2,
                                         unsigned a3, unsigned b0, unsigned b1) {
    asm volatile(
        "mma.sync.aligned.m16n8k16.row.col.f32.bf16.bf16.f32 "
        "{%0,%1,%2,%3}, {%4,%5,%6,%7}, {%8,%9}, {%0,%1,%2,%3};"
        : "+f"(c[0]), "+f"(c[1]), "+f"(c[2]), "+f"(c[3])
        : "r"(a0), "r"(a1), "r"(a2), "r"(a3), "r"(b0), "r"(b1));
}
#define CP_ASYNC16(dst, src) \
    asm volatile("cp.async.cg.shared.global [%0], [%1], 16;" :: "r"(dst), "l"(src))
#define CP_COMMIT asm volatile("cp.async.commit_group;")
#define CP_WAIT1 asm volatile("cp.async.wait_group 1;")
#define CP_WAIT0 asm volatile("cp.async.wait_group 0;")

__device__ __forceinline__ void sts128(unsigned addr, unsigned a, unsigned b,
                                       unsigned c, unsigned d) {
    asm volatile("st.shared.v4.b32 [%0], {%1,%2,%3,%4};"
                 :: "r"(addr), "r"(a), "r"(b), "r"(c), "r"(d));
}
__device__ __forceinline__ float elu1(float v) {
    return (v > 0.0f) ? v : (__expf(v) - 1.0f);
}
__device__ __forceinline__ unsigned hmul2bf(unsigned a, unsigned b) {
    unsigned d;
    asm("mul.bf16x2 %0, %1, %2;" : "=r"(d) : "r"(a), "r"(b));
    return d;
}
__device__ __forceinline__ unsigned hmax2one(unsigned a) {
    unsigned d;
    asm("max.bf16x2 %0, %1, %2;" : "=r"(d) : "r"(a), "r"(0x3f803f80u));
    return d;
}
__device__ __forceinline__ unsigned mpair(unsigned mb, int s) {
    return (((mb >> s) & 1u) ? 0x0000FFFFu : 0u) | (((mb >> s) & 2u) ? 0xFFFF0000u : 0u);
}

// ---------------- kernel 1: convert feature/W to bf16 ----------------
__global__ void prep_kernel(const float* __restrict__ feature, const float* __restrict__ W) {
    int i = blockIdx.x * 256 + threadIdx.x;          // 524288 threads
    #pragma unroll
    for (int r = 0; r < 4; r++) {
        int k = i + r * 524288;                       // NN*FF
        g_featb[k] = __float2bfloat16(feature[k]);
    }
    g_Wb[i] = __float2bfloat16(W[i]);                // HH*FF*DD
}

// ---------------- kernel 2: adjacency -> bitmask ----------------
__global__ void pack_adj_kernel(const int* __restrict__ adj) {
    int gid = blockIdx.x * 256 + threadIdx.x;
    int w = gid >> 5;
    int lane = gid & 31;
    unsigned mask = __ballot_sync(0xffffffffu, adj[(size_t)w * 32 + lane] > 0);
    if (lane == 0) g_adjbits[w] = mask;
}

// ---------------- kernel 3: Wh = feature @ W[h]; epilogue emits e2p*Wh, ratio, e2r ----------------
__global__ void __launch_bounds__(256, 2) proj_kernel(const float* __restrict__ a1,
                                                      const float* __restrict__ a2) {
    __shared__ __nv_bfloat16 sA[128][72];
    __shared__ __nv_bfloat16 sB[64][136];
    __shared__ float sA1[128], sA2[128];

    int h = blockIdx.y;
    int rowbase = blockIdx.x * 128;
    int t = threadIdx.x;
    int warp = t >> 5, lane = t & 31;
    int g = lane >> 2, tid4 = lane & 3;
    int m0 = warp * 16;
    int lr = (lane & 7) + ((lane & 8) ? 8 : 0);
    int lc = (lane & 16) ? 8 : 0;

    if (t < 128) sA1[t] = a1[h * DD + t];
    else sA2[t - 128] = a2[h * DD + (t - 128)];

    float acc[16][4];
    #pragma unroll
    for (int i = 0; i < 16; i++)
        #pragma unroll
        for (int j = 0; j < 4; j++) acc[i][j] = 0.0f;

    for (int kc = 0; kc < FF; kc += 64) {
        __syncthreads();
        const uint4* gA = (const uint4*)(g_featb + (size_t)rowbase * FF + kc);
        #pragma unroll
        for (int r = 0; r < 4; r++) {
            int li = r * 256 + t;
            int row = li >> 3, q = li & 7;
            *(uint4*)&sA[row][q * 8] = gA[row * (FF / 8) + q];
        }
        const uint4* gB = (const uint4*)(g_Wb + ((size_t)h * FF + kc) * DD);
        #pragma unroll
        for (int r = 0; r < 4; r++) {
            int li = r * 256 + t;
            int row = li >> 4, q = li & 15;
            *(uint4*)&sB[row][q * 8] = gB[row * 16 + q];
        }
        __syncthreads();

        #pragma unroll
        for (int kk = 0; kk < 64; kk += 16) {
            unsigned a0, a1r, a2r, a3;
            ldsm_x4(smem_u32(&sA[m0 + lr][kk + lc]), a0, a1r, a2r, a3);
            #pragma unroll
            for (int nb = 0; nb < 8; nb++) {
                unsigned b0, b1, b2, b3;
                ldsm_x4_t(smem_u32(&sB[kk + lr][nb * 16 + lc]), b0, b1, b2, b3);
                mma_bf16(acc[2 * nb], a0, a1r, a2r, a3, b0, b1);
                mma_bf16(acc[2 * nb + 1], a0, a1r, a2r, a3, b2, b3);
            }
        }
    }

    int row_lo = rowbase + m0 + g;
    int row_hi = row_lo + 8;

    // s1/s2 dot products first (need unscaled accs)
    float d1lo = 0, d2lo = 0, d1hi = 0, d2hi = 0;
    #pragma unroll
    for (int i = 0; i < 16; i++) {
        int col = i * 8 + 2 * tid4;
        float v1a = sA1[col], v1b = sA1[col + 1];
        float v2a = sA2[col], v2b = sA2[col + 1];
        d1lo += acc[i][0] * v1a + acc[i][1] * v1b;
        d1hi += acc[i][2] * v1a + acc[i][3] * v1b;
        d2lo += acc[i][0] * v2a + acc[i][1] * v2b;
        d2hi += acc[i][2] * v2a + acc[i][3] * v2b;
    }
    #pragma unroll
    for (int o = 1; o <= 2; o <<= 1) {
        d1lo += __shfl_xor_sync(0xffffffffu, d1lo, o);
        d1hi += __shfl_xor_sync(0xffffffffu, d1hi, o);
        d2lo += __shfl_xor_sync(0xffffffffu, d2lo, o);
        d2hi += __shfl_xor_sync(0xffffffffu, d2hi, o);
    }
    float e2p_lo = __expf(d2lo), e2p_hi = __expf(d2hi);

    // write B' = e2p * Wh (bf16, stride 136)
    __nv_bfloat16* outlo = g_Bp + ((size_t)h * NN + row_lo) * 136;
    __nv_bfloat16* outhi = g_Bp + ((size_t)h * NN + row_hi) * 136;
    #pragma unroll
    for (int i = 0; i < 16; i++) {
        int col = i * 8 + 2 * tid4;
        *(unsigned*)(outlo + col) = pack_bf16x2(acc[i][0] * e2p_lo, acc[i][1] * e2p_lo);
        *(unsigned*)(outhi + col) = pack_bf16x2(acc[i][2] * e2p_hi, acc[i][3] * e2p_hi);
    }
    if (tid4 == 0) {
        // cols 128..135: [e2p, 0, 0, 0, 0, 0, 0, 0]
        *(uint4*)(outlo + 128) = make_uint4(pack_bf16x2(e2p_lo, 0.0f), 0u, 0u, 0u);
        *(uint4*)(outhi + 128) = make_uint4(pack_bf16x2(e2p_hi, 0.0f), 0u, 0u, 0u);
        int ilo = h * NN + row_lo, ihi = h * NN + row_hi;
        g_ratio[ilo] = __expf(-0.8f * d1lo);
        g_ratio[ihi] = __expf(-0.8f * d1hi);
        g_e2rb[ilo] = __float2bfloat16(__expf(-0.8f * d2lo));
        g_e2rb[ihi] = __float2bfloat16(__expf(-0.8f * d2hi));
    }
}

// ---------------- kernel 4: fused masked-softmax aggregation ----------------
// 64-row CTAs, 3 CTAs/SM target (24 warps/SM). A_ij = adj*max(1, r_i*e2r_j),
// B = e2p*Wh (+ e2p col for Z). One barrier per chunk (R6 pipeline order).
#define OFF_P   0                      // 2 x 8 KB
#define OFF_B   16384                  // 2 x 16 KB
#define OFF_ZC  49152                  // 2 x 1 KB
#define OFF_E2R 51200                  // 8 KB
#define ATTN_SMEM_BYTES (59392 + 1024)

__global__ void __launch_bounds__(256, 3) attn_kernel() {
    extern __shared__ char smraw[];
    unsigned sb = (smem_u32(smraw) + 1023u) & ~1023u;
    unsigned sP = sb + OFF_P;
    unsigned sBB = sb + OFF_B;
    unsigned sZ = sb + OFF_ZC;
    unsigned sE = sb + OFF_E2R;

    int t = threadIdx.x;
    int lane = t & 31, w = t >> 5;
    int g = lane >> 2, tid4 = lane & 3;
    int mw = w & 3, nw = w >> 2;
    int m0 = mw * 16, n0 = nw * 64;
    int lr = (lane & 7) + ((lane & 8) ? 8 : 0);
    int lc = (lane & 16) ? 8 : 0;
    int h = blockIdx.y;
    int rowbase = blockIdx.x * 64;

    // score-gen mapping: 4 threads per row, 16 cols each
    int prow = t >> 2, q4 = t & 3;
    int srow = rowbase + prow;
    const unsigned* adjrow = &g_adjbits[(size_t)srow * (NN / 32) + (q4 >> 1)];
    int ash = (q4 & 1) * 16;

    // stage e2r table (8 KB) + B(0) + Zcol(0)
    const __nv_bfloat16* e2rsrc = g_e2rb + (size_t)h * NN;
    CP_ASYNC16(sE + t * 16, e2rsrc + t * 8);
    CP_ASYNC16(sE + (t + 256) * 16, e2rsrc + (t + 256) * 8);
    const char* bsrc = (const char*)(g_Bp + (size_t)h * NN * 136);
    #pragma unroll
    for (int r = 0; r < 4; r++) {
        int li = r * 256 + t;
        int row = li >> 4, q = li & 15;
        CP_ASYNC16(sBB + (q >> 3) * 8192 + SWZ(row * 128 + (q & 7) * 16),
                   bsrc + row * 272 + q * 16);
    }
    if (t < 64) CP_ASYNC16(sZ + t * 16, bsrc + t * 272 + 256);
    CP_COMMIT;

    float rf = g_ratio[h * NN + srow];
    unsigned rr = pack_bf16x2(rf, rf);
    unsigned bw = adjrow[0] >> ash;

    CP_WAIT0;
    __syncthreads();

    float acc[8][4];
    #pragma unroll
    for (int i = 0; i < 8; i++)
        #pragma unroll
        for (int j = 0; j < 4; j++) acc[i][j] = 0.0f;
    float zA[4] = {0, 0, 0, 0};

    for (int i = 0; i < NCHUNK; i++) {
        int kc = i * KC;
        unsigned pb = sP + (i & 1) * 8192;
        int last = (i == NCHUNK - 1);

        // ---- score-gen P(i): 16 cols of row prow ----
        {
            unsigned e0, e1, e2, e3, f0, f1, f2, f3;
            unsigned ea = sE + (kc + q4 * 16) * 2;
            asm volatile("ld.shared.v4.b32 {%0,%1,%2,%3}, [%4];"
                         : "=r"(e0), "=r"(e1), "=r"(e2), "=r"(e3) : "r"(ea));
            asm volatile("ld.shared.v4.b32 {%0,%1,%2,%3}, [%4];"
                         : "=r"(f0), "=r"(f1), "=r"(f2), "=r"(f3) : "r"(ea + 16));
            unsigned pa = pb + SWZ(prow * 128 + q4 * 32);
            sts128(pa,
                   hmax2one(hmul2bf(rr, e0)) & mpair(bw, 0),
                   hmax2one(hmul2bf(rr, e1)) & mpair(bw, 2),
                   hmax2one(hmul2bf(rr, e2)) & mpair(bw, 4),
                   hmax2one(hmul2bf(rr, e3)) & mpair(bw, 6));
            sts128(pb + SWZ(prow * 128 + q4 * 32 + 16),
                   hmax2one(hmul2bf(rr, f0)) & mpair(bw, 8),
                   hmax2one(hmul2bf(rr, f1)) & mpair(bw, 10),
                   hmax2one(hmul2bf(rr, f2)) & mpair(bw, 12),
                   hmax2one(hmul2bf(rr, f3)) & mpair(bw, 14));
        }
        if (!last) bw = adjrow[(i + 1) * 2] >> ash;

        __syncthreads();   // P(i) visible; B(i-1)/P(i-1) readers done

        // ---- prefetch B(i+1)/Z(i+1) ----
        if (!last) {
            const char* src = bsrc + (size_t)(kc + KC) * 272;
            unsigned db = sBB + ((i + 1) & 1) * 16384;
            #pragma unroll
            for (int r = 0; r < 4; r++) {
                int li = r * 256 + t;
                int row = li >> 4, q = li & 15;
                CP_ASYNC16(db + (q >> 3) * 8192 + SWZ(row * 128 + (q & 7) * 16),
                           src + row * 272 + q * 16);
            }
            if (t < 64) CP_ASYNC16(sZ + ((i + 1) & 1) * 1024 + t * 16, src + t * 272 + 256);
        }
        CP_COMMIT;
        CP_WAIT1;          // B(i)/Z(i) resident

        // ---- mma(i): warp tile 16 rows x 64 cols ----
        unsigned bh = sBB + (i & 1) * 16384 + nw * 8192;
        unsigned zb = sZ + (i & 1) * 1024;
        #pragma unroll
        for (int kk = 0; kk < 4; kk++) {
            unsigned A0, A1, A2, A3;
            ldsm_x4(pb + SWZ((m0 + lr) * 128 + (kk * 16 + lc) * 2), A0, A1, A2, A3);
            unsigned zb0, zb1;
            ldsm_x2_t(zb + (kk * 16 + (lane & 15)) * 16, zb0, zb1);
            #pragma unroll
            for (int nb4 = 0; nb4 < 4; nb4++) {
                unsigned b0, b1, b2, b3;
                ldsm_x4_t(bh + SWZ((kk * 16 + lr) * 128 + (nb4 * 16 + lc) * 2),
                          b0, b1, b2, b3);
                mma_bf16(acc[2 * nb4],     A0, A1, A2, A3, b0, b1);
                mma_bf16(acc[2 * nb4 + 1], A0, A1, A2, A3, b2, b3);
            }
            mma_bf16(zA, A0, A1, A2, A3, zb0, zb1);
        }
    }

    // Z in col 0 of the N=8 block -> tid4==0; broadcast within quad
    float z0 = __shfl_sync(0xffffffffu, zA[0], lane & ~3);
    float z1 = __shfl_sync(0xffffffffu, zA[2], lane & ~3);
    float i0 = 1.0f / z0, i1 = 1.0f / z1;

    int r0 = rowbase + m0 + g;
    float* o0 = g_haccum + ((size_t)h * NN + r0) * DD;
    float* o1 = o0 + 8 * DD;
    #pragma unroll
    for (int nb = 0; nb < 8; nb++) {
        int col = n0 + nb * 8 + 2 * tid4;
        float2 v0 = make_float2(elu1(acc[nb][0] * i0), elu1(acc[nb][1] * i0));
        float2 v1 = make_float2(elu1(acc[nb][2] * i1), elu1(acc[nb][3] * i1));
        *(float2*)(o0 + col) = v0;
        *(float2*)(o1 + col) = v1;
    }
}

// ---------------- kernel 5: head-sum -> /H -> log_softmax -> mean ----------------
__global__ void final_kernel(float* __restrict__ out) {
    int warp = threadIdx.x >> 5;
    int lane = threadIdx.x & 31;
    int row = blockIdx.x * 8 + warp;               // 512 blocks -> 4096 rows
    float x0 = 0, x1 = 0, x2 = 0, x3 = 0;
    #pragma unroll
    for (int hh = 0; hh < HH; hh++) {
        float4 v = *(const float4*)(g_haccum + ((size_t)hh * NN + row) * DD + lane * 4);
        x0 += v.x; x1 += v.y; x2 += v.z; x3 += v.w;
    }
    x0 *= 0.125f; x1 *= 0.125f; x2 *= 0.125f; x3 *= 0.125f;
    float mx = fmaxf(fmaxf(x0, x1), fmaxf(x2, x3));
    #pragma unroll
    for (int o = 16; o; o >>= 1) mx = fmaxf(mx, __shfl_xor_sync(0xffffffffu, mx, o));
    float se = __expf(x0 - mx) + __expf(x1 - mx) + __expf(x2 - mx) + __expf(x3 - mx);
    float sx = x0 + x1 + x2 + x3;
    #pragma unroll
    for (int o = 16; o; o >>= 1) {
        se += __shfl_xor_sync(0xffffffffu, se, o);
        sx += __shfl_xor_sync(0xffffffffu, sx, o);
    }
    if (lane == 0) out[row] = sx * (1.0f / 128.0f) - mx - logf(se);
}

// ---------------- launch ----------------
extern "C" void kernel_launch(void* const* d_in, const int* in_sizes, int n_in,
                              void* d_out, int out_size) {
    const float* feature = (const float*)d_in[0];
    const int* adj = (const int*)d_in[1];
    const float* W = (const float*)d_in[2];
    const float* a1 = (const float*)d_in[3];
    const float* a2 = (const float*)d_in[4];
    float* out = (float*)d_out;

    static int attr_set = 0;
    if (!attr_set) {
        cudaFuncSetAttribute(attn_kernel, cudaFuncAttributeMaxDynamicSharedMemorySize,
                             ATTN_SMEM_BYTES);
        attr_set = 1;
    }

    prep_kernel<<<2048, 256>>>(feature, W);
    pack_adj_kernel<<<65536, 256>>>(adj);
    proj_kernel<<<dim3(32, 8), 256>>>(a1, a2);
    attn_kernel<<<dim3(64, 8), 256, ATTN_SMEM_BYTES>>>();
    final_kernel<<<512, 256>>>(out);
}

// round 10
// speedup vs baseline: 1.2428x; 1.2428x over previous
#include <cuda_runtime.h>
#include <cuda_bf16.h>
#include <cstdint>

#define NN 4096
#define FF 512
#define DD 128
#define HH 8
#define KC 64
#define NCHUNK (NN / KC)

// ---------------- scratch (static device globals; no allocs) ----------------
__device__ __nv_bfloat16 g_featb[NN * FF];          // 4 MB
__device__ __nv_bfloat16 g_Wb[HH * FF * DD];        // 1 MB
__device__ __nv_bfloat16 g_Bp[HH * NN * 136];       // 8.9 MB: [h][j][0:128]=e2p*Wh, [128]=e2p, [129:136]=0
__device__ float g_ratio[HH * NN];                  // r_i = exp(-0.8 s1)
__device__ __nv_bfloat16 g_e2rb[HH * NN];           // e2r_j = exp(-0.8 s2), bf16
__device__ unsigned g_adjbits[NN * (NN / 32)];      // 2 MB
__device__ float g_haccum[HH * NN * DD];            // 16 MB per-head elu(h')

// ---------------- helpers ----------------
__device__ __forceinline__ unsigned pack_bf16x2(float lo, float hi) {
    unsigned r;
    asm("cvt.rn.bf16x2.f32 %0, %1, %2;" : "=r"(r) : "f"(hi), "f"(lo));
    return r;
}
__device__ __forceinline__ unsigned smem_u32(const void* p) {
    return (unsigned)__cvta_generic_to_shared(p);
}
__device__ __forceinline__ unsigned SWZ(unsigned off) {        // SW128 swizzle
    return off ^ ((off >> 3) & 0x70);
}
__device__ __forceinline__ void ldsm_x4(unsigned addr, unsigned& r0, unsigned& r1,
                                        unsigned& r2, unsigned& r3) {
    asm volatile("ldmatrix.sync.aligned.m8n8.x4.shared.b16 {%0,%1,%2,%3}, [%4];"
                 : "=r"(r0), "=r"(r1), "=r"(r2), "=r"(r3) : "r"(addr));
}
__device__ __forceinline__ void ldsm_x4_t(unsigned addr, unsigned& r0, unsigned& r1,
                                          unsigned& r2, unsigned& r3) {
    asm volatile("ldmatrix.sync.aligned.m8n8.x4.trans.shared.b16 {%0,%1,%2,%3}, [%4];"
                 : "=r"(r0), "=r"(r1), "=r"(r2), "=r"(r3) : "r"(addr));
}
__device__ __forceinline__ void ldsm_x2_t(unsigned addr, unsigned& r0, unsigned& r1) {
    asm volatile("ldmatrix.sync.aligned.m8n8.x2.trans.shared.b16 {%0,%1}, [%2];"
                 : "=r"(r0), "=r"(r1) : "r"(addr));
}
__device__ __forceinline__ void mma_bf16(float* c, unsigned a0, unsigned a1, unsigned a2,
                                         unsigned a3, unsigned b0, unsigned b1) {
    asm volatile(
        "mma.sync.aligned.m16n8k16.row.col.f32.bf16.bf16.f32 "
        "{%0,%1,%2,%3}, {%4,%5,%6,%7}, {%8,%9}, {%0,%1,%2,%3};"
        : "+f"(c[0]), "+f"(c[1]), "+f"(c[2]), "+f"(c[3])
        : "r"(a0), "r"(a1), "r"(a2), "r"(a3), "r"(b0), "r"(b1));
}
#define CP_ASYNC16(dst, src) \
    asm volatile("cp.async.cg.shared.global [%0], [%1], 16;" :: "r"(dst), "l"(src))
#define CP_COMMIT asm volatile("cp.async.commit_group;")
#define CP_WAIT1 asm volatile("cp.async.wait_group 1;")
#define CP_WAIT0 asm volatile("cp.async.wait_group 0;")

__device__ __forceinline__ void sts128(unsigned addr, unsigned a, unsigned b,
                                       unsigned c, unsigned d) {
    asm volatile("st.shared.v4.b32 [%0], {%1,%2,%3,%4};"
                 :: "r"(addr), "r"(a), "r"(b), "r"(c), "r"(d));
}
__device__ __forceinline__ float elu1(float v) {
    return (v > 0.0f) ? v : (__expf(v) - 1.0f);
}
__device__ __forceinline__ unsigned hmul2bf(unsigned a, unsigned b) {
    unsigned d;
    asm("mul.bf16x2 %0, %1, %2;" : "=r"(d) : "r"(a), "r"(b));
    return d;
}
__device__ __forceinline__ unsigned hmax2one(unsigned a) {
    unsigned d;
    asm("max.bf16x2 %0, %1, %2;" : "=r"(d) : "r"(a), "r"(0x3f803f80u));
    return d;
}
__device__ __forceinline__ unsigned mpair(unsigned mb, int s) {
    return (((mb >> s) & 1u) ? 0x0000FFFFu : 0u) | (((mb >> s) & 2u) ? 0xFFFF0000u : 0u);
}

// ---------------- kernel 1: convert feature/W to bf16 ----------------
__global__ void prep_kernel(const float* __restrict__ feature, const float* __restrict__ W) {
    int i = blockIdx.x * 256 + threadIdx.x;          // 524288 threads
    #pragma unroll
    for (int r = 0; r < 4; r++) {
        int k = i + r * 524288;                       // NN*FF
        g_featb[k] = __float2bfloat16(feature[k]);
    }
    g_Wb[i] = __float2bfloat16(W[i]);                // HH*FF*DD
}

// ---------------- kernel 2: adjacency -> bitmask ----------------
__global__ void pack_adj_kernel(const int* __restrict__ adj) {
    int gid = blockIdx.x * 256 + threadIdx.x;
    int w = gid >> 5;
    int lane = gid & 31;
    unsigned mask = __ballot_sync(0xffffffffu, adj[(size_t)w * 32 + lane] > 0);
    if (lane == 0) g_adjbits[w] = mask;
}

// ---------------- kernel 3: Wh = feature @ W[h]; epilogue emits e2p*Wh, ratio, e2r ----------------
__global__ void __launch_bounds__(256, 2) proj_kernel(const float* __restrict__ a1,
                                                      const float* __restrict__ a2) {
    __shared__ __nv_bfloat16 sA[128][72];
    __shared__ __nv_bfloat16 sB[64][136];
    __shared__ float sA1[128], sA2[128];

    int h = blockIdx.y;
    int rowbase = blockIdx.x * 128;
    int t = threadIdx.x;
    int warp = t >> 5, lane = t & 31;
    int g = lane >> 2, tid4 = lane & 3;
    int m0 = warp * 16;
    int lr = (lane & 7) + ((lane & 8) ? 8 : 0);
    int lc = (lane & 16) ? 8 : 0;

    if (t < 128) sA1[t] = a1[h * DD + t];
    else sA2[t - 128] = a2[h * DD + (t - 128)];

    float acc[16][4];
    #pragma unroll
    for (int i = 0; i < 16; i++)
        #pragma unroll
        for (int j = 0; j < 4; j++) acc[i][j] = 0.0f;

    for (int kc = 0; kc < FF; kc += 64) {
        __syncthreads();
        const uint4* gA = (const uint4*)(g_featb + (size_t)rowbase * FF + kc);
        #pragma unroll
        for (int r = 0; r < 4; r++) {
            int li = r * 256 + t;
            int row = li >> 3, q = li & 7;
            *(uint4*)&sA[row][q * 8] = gA[row * (FF / 8) + q];
        }
        const uint4* gB = (const uint4*)(g_Wb + ((size_t)h * FF + kc) * DD);
        #pragma unroll
        for (int r = 0; r < 4; r++) {
            int li = r * 256 + t;
            int row = li >> 4, q = li & 15;
            *(uint4*)&sB[row][q * 8] = gB[row * 16 + q];
        }
        __syncthreads();

        #pragma unroll
        for (int kk = 0; kk < 64; kk += 16) {
            unsigned a0, a1r, a2r, a3;
            ldsm_x4(smem_u32(&sA[m0 + lr][kk + lc]), a0, a1r, a2r, a3);
            #pragma unroll
            for (int nb = 0; nb < 8; nb++) {
                unsigned b0, b1, b2, b3;
                ldsm_x4_t(smem_u32(&sB[kk + lr][nb * 16 + lc]), b0, b1, b2, b3);
                mma_bf16(acc[2 * nb], a0, a1r, a2r, a3, b0, b1);
                mma_bf16(acc[2 * nb + 1], a0, a1r, a2r, a3, b2, b3);
            }
        }
    }

    int row_lo = rowbase + m0 + g;
    int row_hi = row_lo + 8;

    // s1/s2 dot products first (need unscaled accs)
    float d1lo = 0, d2lo = 0, d1hi = 0, d2hi = 0;
    #pragma unroll
    for (int i = 0; i < 16; i++) {
        int col = i * 8 + 2 * tid4;
        float v1a = sA1[col], v1b = sA1[col + 1];
        float v2a = sA2[col], v2b = sA2[col + 1];
        d1lo += acc[i][0] * v1a + acc[i][1] * v1b;
        d1hi += acc[i][2] * v1a + acc[i][3] * v1b;
        d2lo += acc[i][0] * v2a + acc[i][1] * v2b;
        d2hi += acc[i][2] * v2a + acc[i][3] * v2b;
    }
    #pragma unroll
    for (int o = 1; o <= 2; o <<= 1) {
        d1lo += __shfl_xor_sync(0xffffffffu, d1lo, o);
        d1hi += __shfl_xor_sync(0xffffffffu, d1hi, o);
        d2lo += __shfl_xor_sync(0xffffffffu, d2lo, o);
        d2hi += __shfl_xor_sync(0xffffffffu, d2hi, o);
    }
    float e2p_lo = __expf(d2lo), e2p_hi = __expf(d2hi);

    // write B' = e2p * Wh (bf16, stride 136)
    __nv_bfloat16* outlo = g_Bp + ((size_t)h * NN + row_lo) * 136;
    __nv_bfloat16* outhi = g_Bp + ((size_t)h * NN + row_hi) * 136;
    #pragma unroll
    for (int i = 0; i < 16; i++) {
        int col = i * 8 + 2 * tid4;
        *(unsigned*)(outlo + col) = pack_bf16x2(acc[i][0] * e2p_lo, acc[i][1] * e2p_lo);
        *(unsigned*)(outhi + col) = pack_bf16x2(acc[i][2] * e2p_hi, acc[i][3] * e2p_hi);
    }
    if (tid4 == 0) {
        // cols 128..135: [e2p, 0, 0, 0, 0, 0, 0, 0]
        *(uint4*)(outlo + 128) = make_uint4(pack_bf16x2(e2p_lo, 0.0f), 0u, 0u, 0u);
        *(uint4*)(outhi + 128) = make_uint4(pack_bf16x2(e2p_hi, 0.0f), 0u, 0u, 0u);
        int ilo = h * NN + row_lo, ihi = h * NN + row_hi;
        g_ratio[ilo] = __expf(-0.8f * d1lo);
        g_ratio[ihi] = __expf(-0.8f * d1hi);
        g_e2rb[ilo] = __float2bfloat16(__expf(-0.8f * d2lo));
        g_e2rb[ihi] = __float2bfloat16(__expf(-0.8f * d2hi));
    }
}

// ---------------- kernel 4: fused masked-softmax aggregation ----------------
// R6 structure (measured best): 128-row CTAs, P-in-smem, bf16-SIMD score-gen,
// one barrier per chunk. NEW: Z-mma/Z-ldsm deduped to nw==0 warps only;
// 1/Z broadcast through smem at the epilogue.
#define OFF_P   0
#define OFF_B   32768
#define OFF_ZC  65536
#define OFF_E2R 67584
#define ATTN_SMEM_BYTES (75776 + 1024)

__global__ void __launch_bounds__(256, 2) attn_kernel() {
    extern __shared__ char smraw[];
    unsigned sb = (smem_u32(smraw) + 1023u) & ~1023u;
    unsigned sP = sb + OFF_P;
    unsigned sBB = sb + OFF_B;
    unsigned sZ = sb + OFF_ZC;
    unsigned sE = sb + OFF_E2R;

    int t = threadIdx.x;
    int lane = t & 31, w = t >> 5;
    int g = lane >> 2, tid4 = lane & 3;
    int mw = w & 3, nw = w >> 2;
    int m0 = mw * 32, n0 = nw * 64;
    int lr = (lane & 7) + ((lane & 8) ? 8 : 0);
    int lc = (lane & 16) ? 8 : 0;
    int h = blockIdx.y;
    int rowbase = blockIdx.x * 128;

    int prow = t >> 1, phalf = t & 1;
    int srow = rowbase + prow;
    const unsigned* adjrow = &g_adjbits[(size_t)srow * (NN / 32) + phalf];

    // stage e2r table (8 KB) + B(0) + Zcol(0)
    const __nv_bfloat16* e2rsrc = g_e2rb + (size_t)h * NN;
    CP_ASYNC16(sE + t * 16, e2rsrc + t * 8);
    CP_ASYNC16(sE + (t + 256) * 16, e2rsrc + (t + 256) * 8);
    const char* bsrc = (const char*)(g_Bp + (size_t)h * NN * 136);
    #pragma unroll
    for (int r = 0; r < 4; r++) {
        int li = r * 256 + t;
        int row = li >> 4, q = li & 15;
        CP_ASYNC16(sBB + (q >> 3) * 8192 + SWZ(row * 128 + (q & 7) * 16),
                   bsrc + row * 272 + q * 16);
    }
    if (t < 64) CP_ASYNC16(sZ + t * 16, bsrc + t * 272 + 256);
    CP_COMMIT;

    float rf = g_ratio[h * NN + srow];
    unsigned rr = pack_bf16x2(rf, rf);
    unsigned bw = adjrow[0];

    CP_WAIT0;
    __syncthreads();

    float acc[16][4];
    #pragma unroll
    for (int i = 0; i < 16; i++)
        #pragma unroll
        for (int j = 0; j < 4; j++) acc[i][j] = 0.0f;
    float zA[4] = {0, 0, 0, 0}, zB[4] = {0, 0, 0, 0};

    for (int i = 0; i < NCHUNK; i++) {
        int kc = i * KC;
        unsigned pb = sP + (i & 1) * 16384;
        int last = (i == NCHUNK - 1);

        // ---- score-gen: A row prow, 32 cols (bf16 SIMD) ----
        #pragma unroll
        for (int gi = 0; gi < 4; gi++) {
            int c = phalf * 32 + gi * 8;
            unsigned ex, ey, ez, ew;
            asm volatile("ld.shared.v4.b32 {%0,%1,%2,%3}, [%4];"
                         : "=r"(ex), "=r"(ey), "=r"(ez), "=r"(ew)
                         : "r"(sE + (kc + c) * 2));
            unsigned mb = bw >> (gi * 8);
            sts128(pb + SWZ(prow * 128 + c * 2),
                   hmax2one(hmul2bf(rr, ex)) & mpair(mb, 0),
                   hmax2one(hmul2bf(rr, ey)) & mpair(mb, 2),
                   hmax2one(hmul2bf(rr, ez)) & mpair(mb, 4),
                   hmax2one(hmul2bf(rr, ew)) & mpair(mb, 6));
        }
        if (!last) bw = adjrow[(i + 1) * 2];

        __syncthreads();   // P(i) visible; previous chunk's readers retired

        // ---- prefetch B(i+1)/Z(i+1) ----
        if (!last) {
            const char* src = bsrc + (size_t)(kc + KC) * 272;
            unsigned db = sBB + ((i + 1) & 1) * 16384;
            #pragma unroll
            for (int r = 0; r < 4; r++) {
                int li = r * 256 + t;
                int row = li >> 4, q = li & 15;
                CP_ASYNC16(db + (q >> 3) * 8192 + SWZ(row * 128 + (q & 7) * 16),
                           src + row * 272 + q * 16);
            }
            if (t < 64) CP_ASYNC16(sZ + ((i + 1) & 1) * 1024 + t * 16, src + t * 272 + 256);
        }
        CP_COMMIT;
        CP_WAIT1;          // B(i)/Z(i) resident

        // ---- mma(i) ----
        unsigned bh = sBB + (i & 1) * 16384 + nw * 8192;
        unsigned zb = sZ + (i & 1) * 1024;
        #pragma unroll
        for (int kk = 0; kk < 4; kk++) {
            unsigned A00, A01, A02, A03, A10, A11, A12, A13;
            ldsm_x4(pb + SWZ((m0 + lr) * 128 + (kk * 16 + lc) * 2), A00, A01, A02, A03);
            ldsm_x4(pb + SWZ((m0 + 16 + lr) * 128 + (kk * 16 + lc) * 2), A10, A11, A12, A13);
            #pragma unroll
            for (int nb4 = 0; nb4 < 4; nb4++) {
                unsigned b0, b1, b2, b3;
                ldsm_x4_t(bh + SWZ((kk * 16 + lr) * 128 + (nb4 * 16 + lc) * 2),
                          b0, b1, b2, b3);
                mma_bf16(acc[2 * nb4],     A00, A01, A02, A03, b0, b1);
                mma_bf16(acc[2 * nb4 + 1], A00, A01, A02, A03, b2, b3);
                mma_bf16(acc[8 + 2 * nb4],     A10, A11, A12, A13, b0, b1);
                mma_bf16(acc[8 + 2 * nb4 + 1], A10, A11, A12, A13, b2, b3);
            }
            // Z only on nw==0 warps (nw==1 would duplicate the same result)
            if (nw == 0) {
                unsigned zb0, zb1;
                ldsm_x2_t(zb + (kk * 16 + (lane & 15)) * 16, zb0, zb1);
                mma_bf16(zA, A00, A01, A02, A03, zb0, zb1);
                mma_bf16(zB, A10, A11, A12, A13, zb0, zb1);
            }
        }
    }

    // publish 1/Z: nw==0, tid4==0 threads hold z for rows m0+g(+8,+16,+24)
    __syncthreads();                 // all Z-ldsm of last chunk retired
    if (nw == 0 && tid4 == 0) {
        asm volatile("st.shared.f32 [%0], %1;" :: "r"(sZ + (m0 + g) * 4),      "f"(1.0f / zA[0]));
        asm volatile("st.shared.f32 [%0], %1;" :: "r"(sZ + (m0 + g + 8) * 4),  "f"(1.0f / zA[2]));
        asm volatile("st.shared.f32 [%0], %1;" :: "r"(sZ + (m0 + g + 16) * 4), "f"(1.0f / zB[0]));
        asm volatile("st.shared.f32 [%0], %1;" :: "r"(sZ + (m0 + g + 24) * 4), "f"(1.0f / zB[2]));
    }
    __syncthreads();
    float i0, i1, i2, i3;
    asm volatile("ld.shared.f32 %0, [%1];" : "=f"(i0) : "r"(sZ + (m0 + g) * 4));
    asm volatile("ld.shared.f32 %0, [%1];" : "=f"(i1) : "r"(sZ + (m0 + g + 8) * 4));
    asm volatile("ld.shared.f32 %0, [%1];" : "=f"(i2) : "r"(sZ + (m0 + g + 16) * 4));
    asm volatile("ld.shared.f32 %0, [%1];" : "=f"(i3) : "r"(sZ + (m0 + g + 24) * 4));

    int r0 = rowbase + m0 + g;
    float* o0 = g_haccum + ((size_t)h * NN + r0) * DD;
    float* o1 = o0 + 8 * DD;
    float* o2 = o0 + 16 * DD;
    float* o3 = o0 + 24 * DD;
    #pragma unroll
    for (int nb = 0; nb < 8; nb++) {
        int col = n0 + nb * 8 + 2 * tid4;
        float2 v0 = make_float2(elu1(acc[nb][0] * i0), elu1(acc[nb][1] * i0));
        float2 v1 = make_float2(elu1(acc[nb][2] * i1), elu1(acc[nb][3] * i1));
        float2 v2 = make_float2(elu1(acc[8 + nb][0] * i2), elu1(acc[8 + nb][1] * i2));
        float2 v3 = make_float2(elu1(acc[8 + nb][2] * i3), elu1(acc[8 + nb][3] * i3));
        *(float2*)(o0 + col) = v0;
        *(float2*)(o1 + col) = v1;
        *(float2*)(o2 + col) = v2;
        *(float2*)(o3 + col) = v3;
    }
}

// ---------------- kernel 5: head-sum -> /H -> log_softmax -> mean ----------------
__global__ void final_kernel(float* __restrict__ out) {
    int warp = threadIdx.x >> 5;
    int lane = threadIdx.x & 31;
    int row = blockIdx.x * 8 + warp;               // 512 blocks -> 4096 rows
    float x0 = 0, x1 = 0, x2 = 0, x3 = 0;
    #pragma unroll
    for (int hh = 0; hh < HH; hh++) {
        float4 v = *(const float4*)(g_haccum + ((size_t)hh * NN + row) * DD + lane * 4);
        x0 += v.x; x1 += v.y; x2 += v.z; x3 += v.w;
    }
    x0 *= 0.125f; x1 *= 0.125f; x2 *= 0.125f; x3 *= 0.125f;
    float mx = fmaxf(fmaxf(x0, x1), fmaxf(x2, x3));
    #pragma unroll
    for (int o = 16; o; o >>= 1) mx = fmaxf(mx, __shfl_xor_sync(0xffffffffu, mx, o));
    float se = __expf(x0 - mx) + __expf(x1 - mx) + __expf(x2 - mx) + __expf(x3 - mx);
    float sx = x0 + x1 + x2 + x3;
    #pragma unroll
    for (int o = 16; o; o >>= 1) {
        se += __shfl_xor_sync(0xffffffffu, se, o);
        sx += __shfl_xor_sync(0xffffffffu, sx, o);
    }
    if (lane == 0) out[row] = sx * (1.0f / 128.0f) - mx - logf(se);
}

// ---------------- launch ----------------
extern "C" void kernel_launch(void* const* d_in, const int* in_sizes, int n_in,
                              void* d_out, int out_size) {
    const float* feature = (const float*)d_in[0];
    const int* adj = (const int*)d_in[1];
    const float* W = (const float*)d_in[2];
    const float* a1 = (const float*)d_in[3];
    const float* a2 = (const float*)d_in[4];
    float* out = (float*)d_out;

    static int attr_set = 0;
    if (!attr_set) {
        cudaFuncSetAttribute(attn_kernel, cudaFuncAttributeMaxDynamicSharedMemorySize,
                             ATTN_SMEM_BYTES);
        attr_set = 1;
    }

    prep_kernel<<<2048, 256>>>(feature, W);
    pack_adj_kernel<<<65536, 256>>>(adj);
    proj_kernel<<<dim3(32, 8), 256>>>(a1, a2);
    attn_kernel<<<dim3(32, 8), 256, ATTN_SMEM_BYTES>>>();
    final_kernel<<<512, 256>>>(out);
}